// round 2
// baseline (speedup 1.0000x reference)
#include <cuda_runtime.h>
#include <cstdint>

#define NN 200000
#define NE 800000
#define DD 64
#define NB 8
#define NRR 16

// ---------------- device scratch (no allocations allowed) ----------------
__device__ int g_is64;       // index arrays: 1 if int64, 0 if int32
__device__ int g_mask_mode;  // 0 = 1-byte bool, 1 = int32, 2 = int64
__device__ int g_count[NN];
__device__ int g_off[NN + 1];
__device__ int g_cur[NN];
__device__ unsigned int g_sorted[2 * NE];
__device__ float g_agg[(size_t)NN * 512];   // (N, B*64) fp32, ~410 MB

// ---------------- helpers ----------------
__device__ __forceinline__ int ldidx(const int* p, int i, int is64) {
    return is64 ? p[2 * i] : p[i];
}

__device__ __forceinline__ unsigned long long pack2(float v) {
    unsigned long long r;
    asm("mov.b64 %0, {%1, %1};" : "=l"(r) : "f"(v));
    return r;
}
__device__ __forceinline__ void fma2(unsigned long long& d,
                                     unsigned long long a,
                                     unsigned long long b) {
    asm("fma.rn.f32x2 %0, %1, %2, %0;" : "+l"(d) : "l"(a), "l"(b));
}

// ---------------- K0: sniff index width + mask width ----------------
// Indices: values < 2^31. If int64, all odd 32-bit words are 0.
// Mask: values in {0,1}. If byte-packed bool, some 32-bit word is > 1
// (e.g. 0x01010101). If int64, odd words are all 0. Else int32.
__global__ void sniff_kernel(const unsigned int* idx_words, int n_idx_words,
                             const unsigned int* mask_words, int n_mask) {
    __shared__ int idx_hi_nz, mask_big, mask_hi_nz;
    if (threadIdx.x == 0) { idx_hi_nz = 0; mask_big = 0; mask_hi_nz = 0; }
    __syncthreads();
    int f0 = 0, f1 = 0, f2 = 0;
    for (int i = 1 + 2 * (int)threadIdx.x; i < n_idx_words; i += 2 * blockDim.x)
        f0 |= (idx_words[i] != 0u);
    // scan first n_mask/4 words: safe for any element width >= 1 byte
    for (int i = (int)threadIdx.x; i < n_mask / 4; i += blockDim.x)
        f1 |= (mask_words[i] > 1u);
    // odd words among first n_mask/2: safe for width >= 4 bytes
    for (int i = 1 + 2 * (int)threadIdx.x; i < n_mask / 2; i += 2 * blockDim.x)
        f2 |= (mask_words[i] != 0u);
    if (f0) idx_hi_nz = 1;
    if (f1) mask_big = 1;
    if (f2) mask_hi_nz = 1;
    __syncthreads();
    if (threadIdx.x == 0) {
        g_is64 = idx_hi_nz ? 0 : 1;
        g_mask_mode = mask_big ? 0 : (mask_hi_nz ? 1 : 2);
    }
}

// ---------------- K1: zero histogram ----------------
__global__ void zero_kernel(int N) {
    for (int i = blockIdx.x * blockDim.x + threadIdx.x; i < N;
         i += gridDim.x * blockDim.x)
        g_count[i] = 0;
}

// ---------------- K2: histogram of edge-direction targets ----------------
__global__ void hist_kernel(const int* src, const int* tgt, int E) {
    int is64 = g_is64;
    for (int i = blockIdx.x * blockDim.x + threadIdx.x; i < 2 * E;
         i += gridDim.x * blockDim.x) {
        int t = (i < E) ? ldidx(tgt, i, is64) : ldidx(src, i - E, is64);
        atomicAdd(&g_count[t], 1);
    }
}

// ---------------- K3: single-block exclusive scan (N = 200k) ----------------
__global__ void scan_kernel(int N) {
    __shared__ int ssum[1024];
    int t = threadIdx.x;
    int C = (N + (int)blockDim.x - 1) / (int)blockDim.x;
    int c0 = t * C;
    int s = 0;
    for (int i = 0; i < C; i++) {
        int idx = c0 + i;
        if (idx < N) s += g_count[idx];
    }
    ssum[t] = s;
    __syncthreads();
    for (int off = 1; off < 1024; off <<= 1) {
        int v = (t >= off) ? ssum[t - off] : 0;
        __syncthreads();
        ssum[t] += v;
        __syncthreads();
    }
    int run = ssum[t] - s;  // exclusive prefix for this chunk
    for (int i = 0; i < C; i++) {
        int idx = c0 + i;
        if (idx < N) {
            g_off[idx] = run;
            g_cur[idx] = run;
            run += g_count[idx];
        }
    }
    if (t == 1023) g_off[N] = ssum[1023];
}

// ---------------- K4: scatter edge-directions sorted by target ----------------
__global__ void scatter_kernel(const int* src, const int* tgt, const int* et,
                               int E) {
    int is64 = g_is64;
    for (int i = blockIdx.x * blockDim.x + threadIdx.x; i < 2 * E;
         i += gridDim.x * blockDim.x) {
        int e = (i < E) ? i : i - E;
        int s, t;
        if (i < E) { s = ldidx(src, e, is64); t = ldidx(tgt, e, is64); }
        else       { s = ldidx(tgt, e, is64); t = ldidx(src, e, is64); }
        int r = ldidx(et, e, is64);
        int pos = atomicAdd(&g_cur[t], 1);
        g_sorted[pos] = ((unsigned int)s << 4) | (unsigned int)r;
    }
}

// ---------------- K5: per-node aggregation (warp per node) ----------------
// agg[n,b,d] = sum_{incoming edge-dirs} att[r,b]*x[src,d]  (+ self att row 16)
__global__ void agg_kernel(const float* __restrict__ x,
                           const void* __restrict__ mask,
                           const float* __restrict__ att, int N) {
    __shared__ __align__(16) float4 att_s[34];  // 17 rows x 8 floats
    int tid = threadIdx.x;
    if (tid < 34) att_s[tid] = ((const float4*)att)[tid];
    __syncthreads();

    int warp = tid >> 5, lane = tid & 31;
    int n = blockIdx.x * 8 + warp;
    if (n >= N) return;

    float acc0[8], acc1[8];
#pragma unroll
    for (int b = 0; b < 8; b++) { acc0[b] = 0.f; acc1[b] = 0.f; }

    int beg = g_off[n], end = g_off[n + 1];
    for (int i = beg; i < end; i++) {
        unsigned int p = g_sorted[i];
        int s = (int)(p >> 4);
        int r = (int)(p & 15u);
        float x0 = x[s * 64 + lane];
        float x1 = x[s * 64 + 32 + lane];
        float4 a0 = att_s[r * 2];
        float4 a1 = att_s[r * 2 + 1];
        float ar[8];
        *(float4*)&ar[0] = a0;
        *(float4*)&ar[4] = a1;
#pragma unroll
        for (int b = 0; b < 8; b++) {
            acc0[b] += ar[b] * x0;
            acc1[b] += ar[b] * x1;
        }
    }
    // self-loop, gated by node_keep_mask (width sniffed at runtime)
    int mm = g_mask_mode;
    int keep;
    if (mm == 0)      keep = ((const unsigned char*)mask)[n];
    else if (mm == 1) keep = ((const int*)mask)[n];
    else              keep = ((const int*)mask)[2 * n];
    if (keep) {
        float x0 = x[n * 64 + lane];
        float x1 = x[n * 64 + 32 + lane];
        float4 a0 = att_s[32];
        float4 a1 = att_s[33];
        float ar[8];
        *(float4*)&ar[0] = a0;
        *(float4*)&ar[4] = a1;
#pragma unroll
        for (int b = 0; b < 8; b++) {
            acc0[b] += ar[b] * x0;
            acc1[b] += ar[b] * x1;
        }
    }
    size_t base = (size_t)n * 512;
#pragma unroll
    for (int b = 0; b < 8; b++) {
        g_agg[base + b * 64 + lane]      = acc0[b];
        g_agg[base + b * 64 + 32 + lane] = acc1[b];
    }
}

// ---------------- K6: out = agg (N,512) @ bases (512,64), packed-f32x2 GEMM ----
// Block: 256 threads -> 256 nodes x 64 cols. Thread: 8 nodes x 8 cols.
#define KC 16
__global__ __launch_bounds__(256) void gemm_kernel(
    const float* __restrict__ B, float* __restrict__ out, int N) {
    __shared__ __align__(16) float As[KC][256];
    __shared__ __align__(16) float Bs[KC][64];

    int tid = threadIdx.x;
    int cx = tid & 7;       // cols [8*cx, 8*cx+8)
    int ry = tid >> 3;      // nodes base ry*8
    int nb = blockIdx.x * 256;

    unsigned long long acc[8][4];
#pragma unroll
    for (int i = 0; i < 8; i++)
#pragma unroll
        for (int p = 0; p < 4; p++) acc[i][p] = 0ull;

    for (int kc = 0; kc < 512; kc += KC) {
#pragma unroll
        for (int r = 0; r < 4; r++) {
            int idx = r * 256 + tid;
            int node = idx >> 2;
            int k4 = idx & 3;
            int gn = nb + node;
            float4 v = make_float4(0.f, 0.f, 0.f, 0.f);
            if (gn < N)
                v = *(const float4*)&g_agg[(size_t)gn * 512 + kc + k4 * 4];
            As[k4 * 4 + 0][node] = v.x;
            As[k4 * 4 + 1][node] = v.y;
            As[k4 * 4 + 2][node] = v.z;
            As[k4 * 4 + 3][node] = v.w;
        }
        {
            int row = tid >> 4;
            int c4 = tid & 15;
            float4 v = *(const float4*)&B[(kc + row) * 64 + c4 * 4];
            *(float4*)&Bs[row][c4 * 4] = v;
        }
        __syncthreads();

#pragma unroll
        for (int k = 0; k < KC; k++) {
            float4 a0 = *(const float4*)&As[k][ry * 8];
            float4 a1 = *(const float4*)&As[k][ry * 8 + 4];
            const unsigned long long* bp =
                (const unsigned long long*)&Bs[k][cx * 8];
            unsigned long long pb0 = bp[0], pb1 = bp[1], pb2 = bp[2], pb3 = bp[3];
            unsigned long long pa[8];
            pa[0] = pack2(a0.x); pa[1] = pack2(a0.y);
            pa[2] = pack2(a0.z); pa[3] = pack2(a0.w);
            pa[4] = pack2(a1.x); pa[5] = pack2(a1.y);
            pa[6] = pack2(a1.z); pa[7] = pack2(a1.w);
#pragma unroll
            for (int i = 0; i < 8; i++) {
                fma2(acc[i][0], pa[i], pb0);
                fma2(acc[i][1], pa[i], pb1);
                fma2(acc[i][2], pa[i], pb2);
                fma2(acc[i][3], pa[i], pb3);
            }
        }
        __syncthreads();
    }

#pragma unroll
    for (int i = 0; i < 8; i++) {
        int n = nb + ry * 8 + i;
        if (n < N) {
            unsigned long long* o =
                (unsigned long long*)(out + (size_t)n * 64 + cx * 8);
            ((ulonglong2*)o)[0] = make_ulonglong2(acc[i][0], acc[i][1]);
            ((ulonglong2*)o)[1] = make_ulonglong2(acc[i][2], acc[i][3]);
        }
    }
}

// ---------------- launch ----------------
extern "C" void kernel_launch(void* const* d_in, const int* in_sizes, int n_in,
                              void* d_out, int out_size) {
    const float* x = (const float*)d_in[0];
    const void* mask = d_in[1];
    const int* src = (const int*)d_in[2];
    const int* tgt = (const int*)d_in[3];
    const int* et = (const int*)d_in[4];
    const float* bases = (const float*)d_in[5];
    const float* att = (const float*)d_in[6];
    float* out = (float*)d_out;

    int N = in_sizes[1];  // node_keep_mask element count
    int E = in_sizes[2];  // edge count

    sniff_kernel<<<1, 1024>>>((const unsigned int*)d_in[2], E,
                              (const unsigned int*)d_in[1], N);
    zero_kernel<<<256, 256>>>(N);
    hist_kernel<<<3200, 256>>>(src, tgt, E);
    scan_kernel<<<1, 1024>>>(N);
    scatter_kernel<<<3200, 256>>>(src, tgt, et, E);
    agg_kernel<<<(N + 7) / 8, 256>>>(x, mask, att, N);
    gemm_kernel<<<(N + 255) / 256, 256>>>(bases, out, N);
}

// round 3
// speedup vs baseline: 1.4439x; 1.4439x over previous
#include <cuda_runtime.h>
#include <cstdint>

#define NN 200000
#define NE 800000

// ---------------- device scratch (no allocations allowed) ----------------
__device__ int g_is64;       // index arrays: 1 if int64, 0 if int32
__device__ int g_mask_mode;  // 0 = 1-byte bool, 1 = int32, 2 = int64
__device__ int g_count[NN];
__device__ int g_off[NN + 1];
__device__ int g_cur[NN];
__device__ int g_bsum[256];
__device__ int g_boff[256];
__device__ unsigned int g_sorted[2 * NE];
__device__ float g_agg[(size_t)NN * 512];   // (N, B*64) fp32, ~410 MB

// ---------------- helpers ----------------
__device__ __forceinline__ int ldidx(const int* p, int i, int is64) {
    return is64 ? p[2 * i] : p[i];
}

__device__ __forceinline__ unsigned long long pack2(float v) {
    unsigned long long r;
    asm("mov.b64 %0, {%1, %1};" : "=l"(r) : "f"(v));
    return r;
}
__device__ __forceinline__ void fma2(unsigned long long& d,
                                     unsigned long long a,
                                     unsigned long long b) {
    asm("fma.rn.f32x2 %0, %1, %2, %0;" : "+l"(d) : "l"(a), "l"(b));
}

// ---------------- K0: sniff index width + mask width ----------------
__global__ void sniff_kernel(const unsigned int* idx_words, int n_idx_words,
                             const unsigned int* mask_words, int n_mask) {
    __shared__ int idx_hi_nz, mask_big, mask_hi_nz;
    if (threadIdx.x == 0) { idx_hi_nz = 0; mask_big = 0; mask_hi_nz = 0; }
    __syncthreads();
    int f0 = 0, f1 = 0, f2 = 0;
    for (int i = 1 + 2 * (int)threadIdx.x; i < n_idx_words; i += 2 * blockDim.x)
        f0 |= (idx_words[i] != 0u);
    for (int i = (int)threadIdx.x; i < n_mask / 4; i += blockDim.x)
        f1 |= (mask_words[i] > 1u);
    for (int i = 1 + 2 * (int)threadIdx.x; i < n_mask / 2; i += 2 * blockDim.x)
        f2 |= (mask_words[i] != 0u);
    if (f0) idx_hi_nz = 1;
    if (f1) mask_big = 1;
    if (f2) mask_hi_nz = 1;
    __syncthreads();
    if (threadIdx.x == 0) {
        g_is64 = idx_hi_nz ? 0 : 1;
        g_mask_mode = mask_big ? 0 : (mask_hi_nz ? 1 : 2);
    }
}

// ---------------- K1: zero histogram ----------------
__global__ void zero_kernel(int N) {
    for (int i = blockIdx.x * blockDim.x + threadIdx.x; i < N;
         i += gridDim.x * blockDim.x)
        g_count[i] = 0;
}

// ---------------- K2: histogram of edge-direction targets ----------------
__global__ void hist_kernel(const int* src, const int* tgt, int E) {
    int is64 = g_is64;
    for (int i = blockIdx.x * blockDim.x + threadIdx.x; i < 2 * E;
         i += gridDim.x * blockDim.x) {
        int t = (i < E) ? ldidx(tgt, i, is64) : ldidx(src, i - E, is64);
        atomicAdd(&g_count[t], 1);
    }
}

// ---------------- K3: multi-block exclusive scan (3 passes) ----------------
// Pass A: per-block (1024 elems) partial sums
__global__ void scan1_kernel(int N) {
    __shared__ int red[256];
    int b = blockIdx.x, t = threadIdx.x;
    int base = b * 1024 + t * 4;
    int s = 0;
#pragma unroll
    for (int j = 0; j < 4; j++) {
        int idx = base + j;
        if (idx < N) s += g_count[idx];
    }
    red[t] = s;
    __syncthreads();
    for (int off = 128; off > 0; off >>= 1) {
        if (t < off) red[t] += red[t + off];
        __syncthreads();
    }
    if (t == 0) g_bsum[b] = red[0];
}

// Pass B: scan of block sums (nb <= 256), single block of 256
__global__ void scan2_kernel(int nb, int N) {
    __shared__ int ts[256];
    int t = threadIdx.x;
    int v = (t < nb) ? g_bsum[t] : 0;
    ts[t] = v;
    __syncthreads();
    for (int off = 1; off < 256; off <<= 1) {
        int u = (t >= off) ? ts[t - off] : 0;
        __syncthreads();
        ts[t] += u;
        __syncthreads();
    }
    if (t < nb) g_boff[t] = ts[t] - v;   // exclusive
    if (t == 255) g_off[N] = ts[255];
}

// Pass C: per-block rescan, add block offset, write g_off/g_cur
__global__ void scan3_kernel(int N) {
    __shared__ int ts[256];
    int b = blockIdx.x, t = threadIdx.x;
    int base = b * 1024 + t * 4;
    int c[4];
    int s = 0;
#pragma unroll
    for (int j = 0; j < 4; j++) {
        int idx = base + j;
        c[j] = (idx < N) ? g_count[idx] : 0;
        s += c[j];
    }
    ts[t] = s;
    __syncthreads();
    for (int off = 1; off < 256; off <<= 1) {
        int u = (t >= off) ? ts[t - off] : 0;
        __syncthreads();
        ts[t] += u;
        __syncthreads();
    }
    int run = ts[t] - s + g_boff[b];
#pragma unroll
    for (int j = 0; j < 4; j++) {
        int idx = base + j;
        if (idx < N) {
            g_off[idx] = run;
            g_cur[idx] = run;
            run += c[j];
        }
    }
}

// ---------------- K4: scatter edge-directions sorted by target ----------------
__global__ void scatter_kernel(const int* src, const int* tgt, const int* et,
                               int E) {
    int is64 = g_is64;
    for (int i = blockIdx.x * blockDim.x + threadIdx.x; i < 2 * E;
         i += gridDim.x * blockDim.x) {
        int e = (i < E) ? i : i - E;
        int s, t;
        if (i < E) { s = ldidx(src, e, is64); t = ldidx(tgt, e, is64); }
        else       { s = ldidx(tgt, e, is64); t = ldidx(src, e, is64); }
        int r = ldidx(et, e, is64);
        int pos = atomicAdd(&g_cur[t], 1);
        g_sorted[pos] = ((unsigned int)s << 4) | (unsigned int)r;
    }
}

// ---------------- K5: per-node aggregation (warp per node) ----------------
__global__ void agg_kernel(const float* __restrict__ x,
                           const void* __restrict__ mask,
                           const float* __restrict__ att, int N) {
    __shared__ __align__(16) float4 att_s[34];  // 17 rows x 8 floats
    int tid = threadIdx.x;
    if (tid < 34) att_s[tid] = ((const float4*)att)[tid];
    __syncthreads();

    int warp = tid >> 5, lane = tid & 31;
    int n = blockIdx.x * 8 + warp;
    if (n >= N) return;

    float acc0[8], acc1[8];
#pragma unroll
    for (int b = 0; b < 8; b++) { acc0[b] = 0.f; acc1[b] = 0.f; }

    int beg = g_off[n], end = g_off[n + 1];
    for (int i = beg; i < end; i++) {
        unsigned int p = g_sorted[i];
        int s = (int)(p >> 4);
        int r = (int)(p & 15u);
        float x0 = x[s * 64 + lane];
        float x1 = x[s * 64 + 32 + lane];
        float4 a0 = att_s[r * 2];
        float4 a1 = att_s[r * 2 + 1];
        float ar[8];
        *(float4*)&ar[0] = a0;
        *(float4*)&ar[4] = a1;
#pragma unroll
        for (int b = 0; b < 8; b++) {
            acc0[b] += ar[b] * x0;
            acc1[b] += ar[b] * x1;
        }
    }
    int mm = g_mask_mode;
    int keep;
    if (mm == 0)      keep = ((const unsigned char*)mask)[n];
    else if (mm == 1) keep = ((const int*)mask)[n];
    else              keep = ((const int*)mask)[2 * n];
    if (keep) {
        float x0 = x[n * 64 + lane];
        float x1 = x[n * 64 + 32 + lane];
        float4 a0 = att_s[32];
        float4 a1 = att_s[33];
        float ar[8];
        *(float4*)&ar[0] = a0;
        *(float4*)&ar[4] = a1;
#pragma unroll
        for (int b = 0; b < 8; b++) {
            acc0[b] += ar[b] * x0;
            acc1[b] += ar[b] * x1;
        }
    }
    size_t base = (size_t)n * 512;
#pragma unroll
    for (int b = 0; b < 8; b++) {
        g_agg[base + b * 64 + lane]      = acc0[b];
        g_agg[base + b * 64 + 32 + lane] = acc1[b];
    }
}

// ---------------- K6: out = agg (N,512) @ bases (512,64), packed-f32x2 GEMM ----
#define KC 16
__global__ __launch_bounds__(256) void gemm_kernel(
    const float* __restrict__ B, float* __restrict__ out, int N) {
    __shared__ __align__(16) float As[KC][256];
    __shared__ __align__(16) float Bs[KC][64];

    int tid = threadIdx.x;
    int cx = tid & 7;
    int ry = tid >> 3;
    int nb = blockIdx.x * 256;

    unsigned long long acc[8][4];
#pragma unroll
    for (int i = 0; i < 8; i++)
#pragma unroll
        for (int p = 0; p < 4; p++) acc[i][p] = 0ull;

    for (int kc = 0; kc < 512; kc += KC) {
#pragma unroll
        for (int r = 0; r < 4; r++) {
            int idx = r * 256 + tid;
            int node = idx >> 2;
            int k4 = idx & 3;
            int gn = nb + node;
            float4 v = make_float4(0.f, 0.f, 0.f, 0.f);
            if (gn < N)
                v = *(const float4*)&g_agg[(size_t)gn * 512 + kc + k4 * 4];
            As[k4 * 4 + 0][node] = v.x;
            As[k4 * 4 + 1][node] = v.y;
            As[k4 * 4 + 2][node] = v.z;
            As[k4 * 4 + 3][node] = v.w;
        }
        {
            int row = tid >> 4;
            int c4 = tid & 15;
            float4 v = *(const float4*)&B[(kc + row) * 64 + c4 * 4];
            *(float4*)&Bs[row][c4 * 4] = v;
        }
        __syncthreads();

#pragma unroll
        for (int k = 0; k < KC; k++) {
            float4 a0 = *(const float4*)&As[k][ry * 8];
            float4 a1 = *(const float4*)&As[k][ry * 8 + 4];
            const unsigned long long* bp =
                (const unsigned long long*)&Bs[k][cx * 8];
            unsigned long long pb0 = bp[0], pb1 = bp[1], pb2 = bp[2], pb3 = bp[3];
            unsigned long long pa[8];
            pa[0] = pack2(a0.x); pa[1] = pack2(a0.y);
            pa[2] = pack2(a0.z); pa[3] = pack2(a0.w);
            pa[4] = pack2(a1.x); pa[5] = pack2(a1.y);
            pa[6] = pack2(a1.z); pa[7] = pack2(a1.w);
#pragma unroll
            for (int i = 0; i < 8; i++) {
                fma2(acc[i][0], pa[i], pb0);
                fma2(acc[i][1], pa[i], pb1);
                fma2(acc[i][2], pa[i], pb2);
                fma2(acc[i][3], pa[i], pb3);
            }
        }
        __syncthreads();
    }

#pragma unroll
    for (int i = 0; i < 8; i++) {
        int n = nb + ry * 8 + i;
        if (n < N) {
            unsigned long long* o =
                (unsigned long long*)(out + (size_t)n * 64 + cx * 8);
            ((ulonglong2*)o)[0] = make_ulonglong2(acc[i][0], acc[i][1]);
            ((ulonglong2*)o)[1] = make_ulonglong2(acc[i][2], acc[i][3]);
        }
    }
}

// ---------------- launch ----------------
extern "C" void kernel_launch(void* const* d_in, const int* in_sizes, int n_in,
                              void* d_out, int out_size) {
    const float* x = (const float*)d_in[0];
    const void* mask = d_in[1];
    const int* src = (const int*)d_in[2];
    const int* tgt = (const int*)d_in[3];
    const int* et = (const int*)d_in[4];
    const float* bases = (const float*)d_in[5];
    const float* att = (const float*)d_in[6];
    float* out = (float*)d_out;

    int N = in_sizes[1];
    int E = in_sizes[2];
    int nb = (N + 1023) / 1024;

    sniff_kernel<<<1, 1024>>>((const unsigned int*)d_in[2], E,
                              (const unsigned int*)d_in[1], N);
    zero_kernel<<<256, 256>>>(N);
    hist_kernel<<<3200, 256>>>(src, tgt, E);
    scan1_kernel<<<nb, 256>>>(N);
    scan2_kernel<<<1, 256>>>(nb, N);
    scan3_kernel<<<nb, 256>>>(N);
    scatter_kernel<<<3200, 256>>>(src, tgt, et, E);
    agg_kernel<<<(N + 7) / 8, 256>>>(x, mask, att, N);
    gemm_kernel<<<(N + 255) / 256, 256>>>(bases, out, N);
}

// round 5
// speedup vs baseline: 1.4899x; 1.0318x over previous
#include <cuda_runtime.h>
#include <cstdint>

#define NN 200000
#define NE 800000

// ---------------- device scratch (no allocations allowed) ----------------
__device__ int g_is64;
__device__ int g_mask_mode;  // 0 = byte bool, 1 = int32, 2 = int64
__device__ unsigned int g_flags[3];
__device__ int g_count[NN];
__device__ int g_off[NN + 1];
__device__ int g_cur[NN];
__device__ int g_bsum[256];
__device__ int g_boff[256];
__device__ unsigned int g_sorted[2 * NE];

// ---------------- helpers ----------------
__device__ __forceinline__ int ldidx(const int* p, int i, int is64) {
    return is64 ? p[2 * i] : p[i];
}
__device__ __forceinline__ unsigned long long pack2(float v) {
    unsigned long long r;
    asm("mov.b64 %0, {%1, %1};" : "=l"(r) : "f"(v));
    return r;
}
__device__ __forceinline__ void fma2(unsigned long long& d,
                                     unsigned long long a,
                                     unsigned long long b) {
    asm("fma.rn.f32x2 %0, %1, %2, %0;" : "+l"(d) : "l"(a), "l"(b));
}

// ---------------- K0a: zero hist + flags ----------------
__global__ void zero_kernel(int N) {
    int i0 = blockIdx.x * blockDim.x + threadIdx.x;
    if (i0 < 3) g_flags[i0] = 0u;
    for (int i = i0; i < N; i += gridDim.x * blockDim.x) g_count[i] = 0;
}

// ---------------- K0b: parallel dtype sniff ----------------
__global__ void sniff_kernel(const unsigned int* idx_words, int n_idx_words,
                             const unsigned int* mask_words, int n_mask) {
    int i0 = blockIdx.x * blockDim.x + threadIdx.x;
    int stride = gridDim.x * blockDim.x;
    unsigned f0 = 0, f1 = 0, f2 = 0;
    for (int i = 1 + 2 * i0; i < n_idx_words; i += 2 * stride)
        f0 |= (idx_words[i] != 0u);
    for (int i = i0; i < n_mask / 4; i += stride)
        f1 |= (mask_words[i] > 1u);
    for (int i = 1 + 2 * i0; i < n_mask / 2; i += 2 * stride)
        f2 |= (mask_words[i] != 0u);
    if (f0) atomicOr(&g_flags[0], 1u);
    if (f1) atomicOr(&g_flags[1], 1u);
    if (f2) atomicOr(&g_flags[2], 1u);
}

__global__ void finalize_sniff_kernel() {
    g_is64 = g_flags[0] ? 0 : 1;
    g_mask_mode = g_flags[1] ? 0 : (g_flags[2] ? 1 : 2);
}

// ---------------- K2: histogram of edge-direction targets ----------------
__global__ void hist_kernel(const int* src, const int* tgt, int E) {
    int is64 = g_is64;
    for (int i = blockIdx.x * blockDim.x + threadIdx.x; i < 2 * E;
         i += gridDim.x * blockDim.x) {
        int t = (i < E) ? ldidx(tgt, i, is64) : ldidx(src, i - E, is64);
        atomicAdd(&g_count[t], 1);
    }
}

// ---------------- K3: multi-block exclusive scan (3 passes) ----------------
__global__ void scan1_kernel(int N) {
    __shared__ int red[256];
    int b = blockIdx.x, t = threadIdx.x;
    int base = b * 1024 + t * 4;
    int s = 0;
#pragma unroll
    for (int j = 0; j < 4; j++) {
        int idx = base + j;
        if (idx < N) s += g_count[idx];
    }
    red[t] = s;
    __syncthreads();
    for (int off = 128; off > 0; off >>= 1) {
        if (t < off) red[t] += red[t + off];
        __syncthreads();
    }
    if (t == 0) g_bsum[b] = red[0];
}

__global__ void scan2_kernel(int nb, int N) {
    __shared__ int ts[256];
    int t = threadIdx.x;
    int v = (t < nb) ? g_bsum[t] : 0;
    ts[t] = v;
    __syncthreads();
    for (int off = 1; off < 256; off <<= 1) {
        int u = (t >= off) ? ts[t - off] : 0;
        __syncthreads();
        ts[t] += u;
        __syncthreads();
    }
    if (t < nb) g_boff[t] = ts[t] - v;
    if (t == 255) g_off[N] = ts[255];
}

__global__ void scan3_kernel(int N) {
    __shared__ int ts[256];
    int b = blockIdx.x, t = threadIdx.x;
    int base = b * 1024 + t * 4;
    int c[4];
    int s = 0;
#pragma unroll
    for (int j = 0; j < 4; j++) {
        int idx = base + j;
        c[j] = (idx < N) ? g_count[idx] : 0;
        s += c[j];
    }
    ts[t] = s;
    __syncthreads();
    for (int off = 1; off < 256; off <<= 1) {
        int u = (t >= off) ? ts[t - off] : 0;
        __syncthreads();
        ts[t] += u;
        __syncthreads();
    }
    int run = ts[t] - s + g_boff[b];
#pragma unroll
    for (int j = 0; j < 4; j++) {
        int idx = base + j;
        if (idx < N) {
            g_off[idx] = run;
            g_cur[idx] = run;
            run += c[j];
        }
    }
}

// ---------------- K4: scatter edge-directions sorted by target ----------------
__global__ void scatter_kernel(const int* src, const int* tgt, const int* et,
                               int E) {
    int is64 = g_is64;
    for (int i = blockIdx.x * blockDim.x + threadIdx.x; i < 2 * E;
         i += gridDim.x * blockDim.x) {
        int e = (i < E) ? i : i - E;
        int s, t;
        if (i < E) { s = ldidx(src, e, is64); t = ldidx(tgt, e, is64); }
        else       { s = ldidx(tgt, e, is64); t = ldidx(src, e, is64); }
        int r = ldidx(et, e, is64);
        int pos = atomicAdd(&g_cur[t], 1);
        g_sorted[pos] = ((unsigned int)s << 4) | (unsigned int)r;
    }
}

// ---------------- K5: fused aggregation + GEMM ----------------
// Tile: 32 nodes per block, 256 threads, 2 CTAs/SM.
// Phase A: warp-per-node aggregation into smem As[k=512][node=32(+1 pad)].
// Phase B: out(32x64) = As(32x512) @ bases(512x64), FFMA2, KC=32 staging.
struct FusedSmem {
    float As[512][33];   // 67,584 B, k-major, padded (conflict-free col writes)
    float Bs[32][64];    // 8,192 B
    float4 att_s[34];    // 544 B
};

__global__ __launch_bounds__(256, 2) void fused_kernel(
    const float* __restrict__ x, const void* __restrict__ mask,
    const float* __restrict__ att, const float* __restrict__ B,
    float* __restrict__ out, int N) {
    extern __shared__ __align__(16) char smem_raw[];
    FusedSmem* sm = (FusedSmem*)smem_raw;

    int tid = threadIdx.x;
    if (tid < 34) sm->att_s[tid] = ((const float4*)att)[tid];
    __syncthreads();

    int warp = tid >> 5, lane = tid & 31;
    int nb = blockIdx.x * 32;
    int mm = g_mask_mode;

    // ---- Phase A: aggregate 4 nodes per warp ----
#pragma unroll 1
    for (int j = 0; j < 4; j++) {
        int nl = warp * 4 + j;
        int n = nb + nl;
        if (n >= N) break;
        float acc0[8], acc1[8];
#pragma unroll
        for (int b = 0; b < 8; b++) { acc0[b] = 0.f; acc1[b] = 0.f; }
        int beg = g_off[n], end = g_off[n + 1];
        for (int i = beg; i < end; i++) {
            unsigned int p = g_sorted[i];
            int s = (int)(p >> 4);
            int r = (int)(p & 15u);
            float x0 = x[s * 64 + lane];
            float x1 = x[s * 64 + 32 + lane];
            float4 a0 = sm->att_s[r * 2];
            float4 a1 = sm->att_s[r * 2 + 1];
            float ar[8];
            *(float4*)&ar[0] = a0;
            *(float4*)&ar[4] = a1;
#pragma unroll
            for (int b = 0; b < 8; b++) {
                acc0[b] += ar[b] * x0;
                acc1[b] += ar[b] * x1;
            }
        }
        int keep;
        if (mm == 0)      keep = ((const unsigned char*)mask)[n];
        else if (mm == 1) keep = ((const int*)mask)[n];
        else              keep = ((const int*)mask)[2 * n];
        if (keep) {
            float x0 = x[n * 64 + lane];
            float x1 = x[n * 64 + 32 + lane];
            float4 a0 = sm->att_s[32];
            float4 a1 = sm->att_s[33];
            float ar[8];
            *(float4*)&ar[0] = a0;
            *(float4*)&ar[4] = a1;
#pragma unroll
            for (int b = 0; b < 8; b++) {
                acc0[b] += ar[b] * x0;
                acc1[b] += ar[b] * x1;
            }
        }
#pragma unroll
        for (int b = 0; b < 8; b++) {
            sm->As[b * 64 + lane][nl]      = acc0[b];
            sm->As[b * 64 + 32 + lane][nl] = acc1[b];
        }
    }
    __syncthreads();

    // ---- Phase B: (32 x 512) @ (512 x 64) ----
    int cx = tid & 15;   // 8 output cols: [4cx, 4cx+4) x2 accum pairs
    int ry = tid >> 4;   // 2 nodes: [2ry, 2ry+2)

    unsigned long long a00 = 0, a01 = 0, a10 = 0, a11 = 0;

    for (int kc = 0; kc < 512; kc += 32) {
        // stage Bs: 2048 floats = 512 float4 by 256 threads
#pragma unroll
        for (int v = 0; v < 2; v++) {
            int fidx = tid + v * 256;
            int row = fidx >> 4;
            int c4 = fidx & 15;
            *(float4*)&sm->Bs[row][c4 * 4] =
                *(const float4*)&B[(kc + row) * 64 + c4 * 4];
        }
        __syncthreads();
#pragma unroll
        for (int kk = 0; kk < 32; kk++) {
            // scalar loads: As row stride is 33 floats (odd), so no float2
            float ax = sm->As[kc + kk][2 * ry];
            float ay = sm->As[kc + kk][2 * ry + 1];
            ulonglong2 bb = *(const ulonglong2*)&sm->Bs[kk][4 * cx];
            unsigned long long pa0 = pack2(ax);
            unsigned long long pa1 = pack2(ay);
            fma2(a00, pa0, bb.x);
            fma2(a01, pa0, bb.y);
            fma2(a10, pa1, bb.x);
            fma2(a11, pa1, bb.y);
        }
        __syncthreads();
    }

    int n0 = nb + 2 * ry;
    if (n0 < N)
        *(ulonglong2*)(out + (size_t)n0 * 64 + 4 * cx) = make_ulonglong2(a00, a01);
    if (n0 + 1 < N)
        *(ulonglong2*)(out + (size_t)(n0 + 1) * 64 + 4 * cx) = make_ulonglong2(a10, a11);
}

// ---------------- launch ----------------
extern "C" void kernel_launch(void* const* d_in, const int* in_sizes, int n_in,
                              void* d_out, int out_size) {
    const float* x = (const float*)d_in[0];
    const void* mask = d_in[1];
    const int* src = (const int*)d_in[2];
    const int* tgt = (const int*)d_in[3];
    const int* et = (const int*)d_in[4];
    const float* bases = (const float*)d_in[5];
    const float* att = (const float*)d_in[6];
    float* out = (float*)d_out;

    int N = in_sizes[1];
    int E = in_sizes[2];
    int nb = (N + 1023) / 1024;
    int smem_bytes = (int)sizeof(FusedSmem);

    cudaFuncSetAttribute(fused_kernel,
                         cudaFuncAttributeMaxDynamicSharedMemorySize,
                         smem_bytes);

    zero_kernel<<<256, 256>>>(N);
    sniff_kernel<<<256, 256>>>((const unsigned int*)d_in[2], E,
                               (const unsigned int*)d_in[1], N);
    finalize_sniff_kernel<<<1, 1>>>();
    hist_kernel<<<3200, 256>>>(src, tgt, E);
    scan1_kernel<<<nb, 256>>>(N);
    scan2_kernel<<<1, 256>>>(nb, N);
    scan3_kernel<<<nb, 256>>>(N);
    scatter_kernel<<<3200, 256>>>(src, tgt, et, E);
    fused_kernel<<<(N + 31) / 32, 256, smem_bytes>>>(x, mask, att, bases, out, N);
}

// round 7
// speedup vs baseline: 2.6491x; 1.7781x over previous
#include <cuda_runtime.h>
#include <cuda_bf16.h>
#include <cstdint>

#define NN 200000
#define NE 800000
#define NPAD 200064   // 1563 * 128

// ---------------- device scratch (no allocations allowed) ----------------
__device__ int g_is64;
__device__ int g_mask_mode;  // 0 = byte bool, 1 = int32, 2 = int64
__device__ unsigned int g_flags[3];
__device__ int g_count[NN];
__device__ int g_off[NN + 1];
__device__ int g_cur[NN];
__device__ int g_bsum[256];
__device__ int g_boff[256];
__device__ unsigned int g_sorted[2 * NE];
__device__ __nv_bfloat16 g_Ahi[(size_t)NPAD * 512];  // 205 MB
__device__ __nv_bfloat16 g_Alo[(size_t)NPAD * 512];  // 205 MB
__device__ __nv_bfloat16 g_Bthi[64 * 512];           // basesT hi (n-major, k-contig)
__device__ __nv_bfloat16 g_Btlo[64 * 512];           // basesT lo

// ---------------- helpers ----------------
__device__ __forceinline__ int ldidx(const int* p, int i, int is64) {
    return is64 ? p[2 * i] : p[i];
}
__device__ __forceinline__ uint32_t smem_u32(const void* p) {
    uint32_t a;
    asm("{ .reg .u64 t; cvta.to.shared.u64 t, %1; cvt.u32.u64 %0, t; }"
        : "=r"(a) : "l"(p));
    return a;
}
__device__ __forceinline__ void ldsm4(uint32_t* r, uint32_t addr) {
    asm volatile("ldmatrix.sync.aligned.m8n8.x4.shared.b16 {%0,%1,%2,%3}, [%4];"
                 : "=r"(r[0]), "=r"(r[1]), "=r"(r[2]), "=r"(r[3]) : "r"(addr));
}
__device__ __forceinline__ void mma16816(float* c, const uint32_t* a,
                                         const uint32_t* b) {
    asm volatile(
        "mma.sync.aligned.m16n8k16.row.col.f32.bf16.bf16.f32 "
        "{%0,%1,%2,%3}, {%4,%5,%6,%7}, {%8,%9}, {%0,%1,%2,%3};"
        : "+f"(c[0]), "+f"(c[1]), "+f"(c[2]), "+f"(c[3])
        : "r"(a[0]), "r"(a[1]), "r"(a[2]), "r"(a[3]), "r"(b[0]), "r"(b[1]));
}

// ---------------- K0a: zero hist + flags ----------------
__global__ void zero_kernel(int N) {
    int i0 = blockIdx.x * blockDim.x + threadIdx.x;
    if (i0 < 3) g_flags[i0] = 0u;
    for (int i = i0; i < N; i += gridDim.x * blockDim.x) g_count[i] = 0;
}

// ---------------- K0b: parallel dtype sniff ----------------
__global__ void sniff_kernel(const unsigned int* idx_words, int n_idx_words,
                             const unsigned int* mask_words, int n_mask) {
    int i0 = blockIdx.x * blockDim.x + threadIdx.x;
    int stride = gridDim.x * blockDim.x;
    unsigned f0 = 0, f1 = 0, f2 = 0;
    for (int i = 1 + 2 * i0; i < n_idx_words; i += 2 * stride)
        f0 |= (idx_words[i] != 0u);
    for (int i = i0; i < n_mask / 4; i += stride)
        f1 |= (mask_words[i] > 1u);
    for (int i = 1 + 2 * i0; i < n_mask / 2; i += 2 * stride)
        f2 |= (mask_words[i] != 0u);
    if (f0) atomicOr(&g_flags[0], 1u);
    if (f1) atomicOr(&g_flags[1], 1u);
    if (f2) atomicOr(&g_flags[2], 1u);
}

__global__ void finalize_sniff_kernel() {
    g_is64 = g_flags[0] ? 0 : 1;
    g_mask_mode = g_flags[1] ? 0 : (g_flags[2] ? 1 : 2);
}

// ---------------- prep: basesT split to bf16 hi/lo ----------------
__global__ void prep_bases_kernel(const float* __restrict__ bases) {
    // bases: (512,64) fp32. BT[n][k] = bases[k][n].
    for (int idx = blockIdx.x * blockDim.x + threadIdx.x; idx < 512 * 64;
         idx += gridDim.x * blockDim.x) {
        int n = idx >> 9, k = idx & 511;
        float v = bases[k * 64 + n];
        __nv_bfloat16 hi = __float2bfloat16(v);
        __nv_bfloat16 lo = __float2bfloat16(v - __bfloat162float(hi));
        g_Bthi[n * 512 + k] = hi;
        g_Btlo[n * 512 + k] = lo;
    }
}

// ---------------- K2: histogram of edge-direction targets ----------------
__global__ void hist_kernel(const int* src, const int* tgt, int E) {
    int is64 = g_is64;
    for (int i = blockIdx.x * blockDim.x + threadIdx.x; i < 2 * E;
         i += gridDim.x * blockDim.x) {
        int t = (i < E) ? ldidx(tgt, i, is64) : ldidx(src, i - E, is64);
        atomicAdd(&g_count[t], 1);
    }
}

// ---------------- K3: multi-block exclusive scan ----------------
__global__ void scan1_kernel(int N) {
    __shared__ int red[256];
    int b = blockIdx.x, t = threadIdx.x;
    int base = b * 1024 + t * 4;
    int s = 0;
#pragma unroll
    for (int j = 0; j < 4; j++) {
        int idx = base + j;
        if (idx < N) s += g_count[idx];
    }
    red[t] = s;
    __syncthreads();
    for (int off = 128; off > 0; off >>= 1) {
        if (t < off) red[t] += red[t + off];
        __syncthreads();
    }
    if (t == 0) g_bsum[b] = red[0];
}

__global__ void scan2_kernel(int nb, int N) {
    __shared__ int ts[256];
    int t = threadIdx.x;
    int v = (t < nb) ? g_bsum[t] : 0;
    ts[t] = v;
    __syncthreads();
    for (int off = 1; off < 256; off <<= 1) {
        int u = (t >= off) ? ts[t - off] : 0;
        __syncthreads();
        ts[t] += u;
        __syncthreads();
    }
    if (t < nb) g_boff[t] = ts[t] - v;
    if (t == 255) g_off[N] = ts[255];
}

__global__ void scan3_kernel(int N) {
    __shared__ int ts[256];
    int b = blockIdx.x, t = threadIdx.x;
    int base = b * 1024 + t * 4;
    int c[4];
    int s = 0;
#pragma unroll
    for (int j = 0; j < 4; j++) {
        int idx = base + j;
        c[j] = (idx < N) ? g_count[idx] : 0;
        s += c[j];
    }
    ts[t] = s;
    __syncthreads();
    for (int off = 1; off < 256; off <<= 1) {
        int u = (t >= off) ? ts[t - off] : 0;
        __syncthreads();
        ts[t] += u;
        __syncthreads();
    }
    int run = ts[t] - s + g_boff[b];
#pragma unroll
    for (int j = 0; j < 4; j++) {
        int idx = base + j;
        if (idx < N) {
            g_off[idx] = run;
            g_cur[idx] = run;
            run += c[j];
        }
    }
}

// ---------------- K4: scatter edges sorted by target ----------------
__global__ void scatter_kernel(const int* src, const int* tgt, const int* et,
                               int E) {
    int is64 = g_is64;
    for (int i = blockIdx.x * blockDim.x + threadIdx.x; i < 2 * E;
         i += gridDim.x * blockDim.x) {
        int e = (i < E) ? i : i - E;
        int s, t;
        if (i < E) { s = ldidx(src, e, is64); t = ldidx(tgt, e, is64); }
        else       { s = ldidx(tgt, e, is64); t = ldidx(src, e, is64); }
        int r = ldidx(et, e, is64);
        int pos = atomicAdd(&g_cur[t], 1);
        g_sorted[pos] = ((unsigned int)s << 4) | (unsigned int)r;
    }
}

// ---------------- K5: aggregation, warp per node, writes bf16 hi/lo ----------
__global__ void agg_kernel(const float* __restrict__ x,
                           const void* __restrict__ mask,
                           const float* __restrict__ att, int N) {
    __shared__ __align__(16) float4 att_s[34];
    int tid = threadIdx.x;
    if (tid < 34) att_s[tid] = ((const float4*)att)[tid];
    __syncthreads();

    int warp = tid >> 5, lane = tid & 31;
    int n = blockIdx.x * 8 + warp;
    if (n >= N) return;

    float acc0[8], acc1[8];
#pragma unroll
    for (int b = 0; b < 8; b++) { acc0[b] = 0.f; acc1[b] = 0.f; }

    int beg = g_off[n], end = g_off[n + 1];
    for (int i = beg; i < end; i++) {
        unsigned int p = g_sorted[i];
        int s = (int)(p >> 4);
        int r = (int)(p & 15u);
        float x0 = x[s * 64 + lane];
        float x1 = x[s * 64 + 32 + lane];
        float4 a0 = att_s[r * 2];
        float4 a1 = att_s[r * 2 + 1];
        float ar[8];
        *(float4*)&ar[0] = a0;
        *(float4*)&ar[4] = a1;
#pragma unroll
        for (int b = 0; b < 8; b++) {
            acc0[b] += ar[b] * x0;
            acc1[b] += ar[b] * x1;
        }
    }
    int mm = g_mask_mode;
    int keep;
    if (mm == 0)      keep = ((const unsigned char*)mask)[n];
    else if (mm == 1) keep = ((const int*)mask)[n];
    else              keep = ((const int*)mask)[2 * n];
    if (keep) {
        float x0 = x[n * 64 + lane];
        float x1 = x[n * 64 + 32 + lane];
        float4 a0 = att_s[32];
        float4 a1 = att_s[33];
        float ar[8];
        *(float4*)&ar[0] = a0;
        *(float4*)&ar[4] = a1;
#pragma unroll
        for (int b = 0; b < 8; b++) {
            acc0[b] += ar[b] * x0;
            acc1[b] += ar[b] * x1;
        }
    }
    size_t base = (size_t)n * 512;
#pragma unroll
    for (int b = 0; b < 8; b++) {
        float v0 = acc0[b], v1 = acc1[b];
        __nv_bfloat16 h0 = __float2bfloat16(v0);
        __nv_bfloat16 h1 = __float2bfloat16(v1);
        g_Ahi[base + b * 64 + lane]      = h0;
        g_Ahi[base + b * 64 + 32 + lane] = h1;
        g_Alo[base + b * 64 + lane]      = __float2bfloat16(v0 - __bfloat162float(h0));
        g_Alo[base + b * 64 + 32 + lane] = __float2bfloat16(v1 - __bfloat162float(h1));
    }
}

// ---------------- K6: mma.sync split-bf16 GEMM ----------------
// CTA: 128 nodes x 64 cols, 256 thr / 8 warps (warp grid 4x2, 32x32 tiles).
// D = Ahi@BThi^T + Alo@BThi^T + Ahi@BTlo^T, fp32 accum.
// smem (bf16): Bhi[64][520], Blo[64][520], Ahi[128][72], Alo[128][72]
#define OFF_BHI 0
#define OFF_BLO 66560
#define OFF_AHI 133120
#define OFF_ALO 151552
#define SMEM_MM 169984

__global__ __launch_bounds__(256, 1) void gemm_mm_kernel(
    float* __restrict__ out, int N) {
    extern __shared__ __align__(16) char sm[];
    uint32_t sbase = smem_u32(sm);
    int tid = threadIdx.x, wid = tid >> 5, lid = tid & 31;
    int nb = blockIdx.x * 128;
    int warp_m = (wid & 3) * 32;   // 0,32,64,96
    int warp_n = (wid >> 2) * 32;  // 0,32

    // ---- stage B (hi+lo) once: 64 rows x 512 k ----
#pragma unroll
    for (int t = 0; t < 16; t++) {
        int idx = t * 256 + tid;
        int row = idx >> 6;
        int cb = (idx & 63) * 16;
        *(uint4*)(sm + OFF_BHI + row * 1040 + cb) =
            *(const uint4*)((const char*)g_Bthi + row * 1024 + cb);
        *(uint4*)(sm + OFF_BLO + row * 1040 + cb) =
            *(const uint4*)((const char*)g_Btlo + row * 1024 + cb);
    }

    float acc[2][4][4];
#pragma unroll
    for (int mt = 0; mt < 2; mt++)
#pragma unroll
        for (int nt = 0; nt < 4; nt++)
#pragma unroll
            for (int q = 0; q < 4; q++) acc[mt][nt][q] = 0.f;

    // per-lane ldmatrix base addresses
    // A tile (m16k16): lane l -> row m_base+(l&15), kbyte (l&16)
    uint32_t a_row0 = (uint32_t)(warp_m + (lid & 15));
    uint32_t a_kb = (uint32_t)(lid & 16);
    uint32_t aaddr_hi0 = sbase + OFF_AHI + a_row0 * 144 + a_kb;
    uint32_t aaddr_hi1 = aaddr_hi0 + 16 * 144;
    uint32_t aaddr_lo0 = sbase + OFF_ALO + a_row0 * 144 + a_kb;
    uint32_t aaddr_lo1 = aaddr_lo0 + 16 * 144;
    // B pair tile (2 x n8 x k16): lane l -> row n_base+(l&7)+((l>>4)&1)*8,
    //                             kbyte ((l>>3)&1)*16
    uint32_t b_row = (uint32_t)(warp_n + (lid & 7) + ((lid >> 4) & 1) * 8);
    uint32_t b_kb = (uint32_t)(((lid >> 3) & 1) * 16);
    uint32_t baddr_hi0 = sbase + OFF_BHI + b_row * 1040 + b_kb;
    uint32_t baddr_hi1 = baddr_hi0 + 16 * 1040;
    uint32_t baddr_lo0 = sbase + OFF_BLO + b_row * 1040 + b_kb;
    uint32_t baddr_lo1 = baddr_lo0 + 16 * 1040;

    for (int c = 0; c < 8; c++) {
        __syncthreads();
        // ---- stage A chunk c: 128 rows x 64 k (hi+lo) ----
#pragma unroll
        for (int t = 0; t < 4; t++) {
            int idx = t * 256 + tid;
            int row = idx >> 3;
            int cb = (idx & 7) * 16;
            size_t gb = (size_t)(nb + row) * 1024 + (size_t)c * 128 + cb;
            *(uint4*)(sm + OFF_AHI + row * 144 + cb) =
                *(const uint4*)((const char*)g_Ahi + gb);
            *(uint4*)(sm + OFF_ALO + row * 144 + cb) =
                *(const uint4*)((const char*)g_Alo + gb);
        }
        __syncthreads();

#pragma unroll
        for (int ks = 0; ks < 4; ks++) {
            uint32_t kb = (uint32_t)(ks * 32);
            uint32_t gkb = (uint32_t)(c * 128) + kb;
            uint32_t ahi[2][4], alo[2][4];
            ldsm4(ahi[0], aaddr_hi0 + kb);
            ldsm4(ahi[1], aaddr_hi1 + kb);
            ldsm4(alo[0], aaddr_lo0 + kb);
            ldsm4(alo[1], aaddr_lo1 + kb);
            uint32_t bh[4], bl[4];  // [pair0: b0,b1 | pair1: b0,b1] x2 pairs
            uint32_t bhp[2][4], blp[2][4];
            ldsm4(bhp[0], baddr_hi0 + gkb);
            ldsm4(bhp[1], baddr_hi1 + gkb);
            ldsm4(blp[0], baddr_lo0 + gkb);
            ldsm4(blp[1], baddr_lo1 + gkb);
#pragma unroll
            for (int mt = 0; mt < 2; mt++) {
#pragma unroll
                for (int nt = 0; nt < 4; nt++) {
                    const uint32_t* bhf = &bhp[nt >> 1][(nt & 1) * 2];
                    const uint32_t* blf = &blp[nt >> 1][(nt & 1) * 2];
                    mma16816(acc[mt][nt], ahi[mt], bhf);
                    mma16816(acc[mt][nt], alo[mt], bhf);
                    mma16816(acc[mt][nt], ahi[mt], blf);
                }
            }
            (void)bh; (void)bl;
        }
    }

    // ---- store: c0,c1 -> (row t/4, col 2(t%4)); c2,c3 -> row+8 ----
    int trow = lid >> 2, tcol = (lid & 3) * 2;
#pragma unroll
    for (int mt = 0; mt < 2; mt++) {
        int m0 = nb + warp_m + mt * 16 + trow;
#pragma unroll
        for (int nt = 0; nt < 4; nt++) {
            int col = warp_n + nt * 8 + tcol;
            if (m0 < N)
                *(float2*)(out + (size_t)m0 * 64 + col) =
                    make_float2(acc[mt][nt][0], acc[mt][nt][1]);
            if (m0 + 8 < N)
                *(float2*)(out + (size_t)(m0 + 8) * 64 + col) =
                    make_float2(acc[mt][nt][2], acc[mt][nt][3]);
        }
    }
}

// ---------------- launch ----------------
extern "C" void kernel_launch(void* const* d_in, const int* in_sizes, int n_in,
                              void* d_out, int out_size) {
    const float* x = (const float*)d_in[0];
    const void* mask = d_in[1];
    const int* src = (const int*)d_in[2];
    const int* tgt = (const int*)d_in[3];
    const int* et = (const int*)d_in[4];
    const float* bases = (const float*)d_in[5];
    const float* att = (const float*)d_in[6];
    float* out = (float*)d_out;

    int N = in_sizes[1];
    int E = in_sizes[2];
    int nb = (N + 1023) / 1024;

    cudaFuncSetAttribute(gemm_mm_kernel,
                         cudaFuncAttributeMaxDynamicSharedMemorySize, SMEM_MM);

    zero_kernel<<<256, 256>>>(N);
    sniff_kernel<<<256, 256>>>((const unsigned int*)d_in[2], E,
                               (const unsigned int*)d_in[1], N);
    finalize_sniff_kernel<<<1, 1>>>();
    prep_bases_kernel<<<128, 256>>>(bases);
    hist_kernel<<<3200, 256>>>(src, tgt, E);
    scan1_kernel<<<nb, 256>>>(N);
    scan2_kernel<<<1, 256>>>(nb, N);
    scan3_kernel<<<nb, 256>>>(N);
    scatter_kernel<<<3200, 256>>>(src, tgt, et, E);
    agg_kernel<<<(N + 7) / 8, 256>>>(x, mask, att, N);
    gemm_mm_kernel<<<(N + 127) / 128, 256, SMEM_MM>>>(out, N);
}

// round 8
// speedup vs baseline: 3.2525x; 1.2278x over previous
#include <cuda_runtime.h>
#include <cuda_fp16.h>
#include <cstdint>

#define NN 200000
#define NE 800000
#define NPAD 200064   // 1563 * 128

// ---------------- device scratch (no allocations allowed) ----------------
__device__ int g_is64;
__device__ int g_mask_mode;  // 0 = byte bool, 1 = int32, 2 = int64
__device__ unsigned int g_flags[3];
__device__ int g_count[NN];
__device__ int g_off[NN + 1];
__device__ int g_cur[NN];
__device__ int g_bsum[256];
__device__ int g_boff[256];
__device__ unsigned int g_sorted[2 * NE];
__device__ __half g_Ahi[(size_t)NPAD * 512];  // 205 MB
__device__ __half g_Alo[(size_t)NPAD * 512];  // 205 MB
__device__ __half g_Bthi[64 * 512];           // basesT fp16 (n-major, k-contig)

// ---------------- helpers ----------------
__device__ __forceinline__ int ldidx(const int* p, int i, int is64) {
    return is64 ? p[2 * i] : p[i];
}
__device__ __forceinline__ uint32_t smem_u32(const void* p) {
    uint32_t a;
    asm("{ .reg .u64 t; cvta.to.shared.u64 t, %1; cvt.u32.u64 %0, t; }"
        : "=r"(a) : "l"(p));
    return a;
}
__device__ __forceinline__ void ldsm4(uint32_t* r, uint32_t addr) {
    asm volatile("ldmatrix.sync.aligned.m8n8.x4.shared.b16 {%0,%1,%2,%3}, [%4];"
                 : "=r"(r[0]), "=r"(r[1]), "=r"(r[2]), "=r"(r[3]) : "r"(addr));
}
__device__ __forceinline__ void mma16816(float* c, const uint32_t* a,
                                         const uint32_t* b) {
    asm volatile(
        "mma.sync.aligned.m16n8k16.row.col.f32.f16.f16.f32 "
        "{%0,%1,%2,%3}, {%4,%5,%6,%7}, {%8,%9}, {%0,%1,%2,%3};"
        : "+f"(c[0]), "+f"(c[1]), "+f"(c[2]), "+f"(c[3])
        : "r"(a[0]), "r"(a[1]), "r"(a[2]), "r"(a[3]), "r"(b[0]), "r"(b[1]));
}
__device__ __forceinline__ void cp16(uint32_t saddr, const void* gptr) {
    asm volatile("cp.async.cg.shared.global [%0], [%1], 16;"
                 :: "r"(saddr), "l"(gptr) : "memory");
}
#define CP_COMMIT() asm volatile("cp.async.commit_group;" ::: "memory")
#define CP_WAIT(n)  asm volatile("cp.async.wait_group %0;" :: "n"(n) : "memory")

// ---------------- K0a: zero hist + flags ----------------
__global__ void zero_kernel(int N) {
    int i0 = blockIdx.x * blockDim.x + threadIdx.x;
    if (i0 < 3) g_flags[i0] = 0u;
    for (int i = i0; i < N; i += gridDim.x * blockDim.x) g_count[i] = 0;
}

// ---------------- K0b: parallel dtype sniff ----------------
__global__ void sniff_kernel(const unsigned int* idx_words, int n_idx_words,
                             const unsigned int* mask_words, int n_mask) {
    int i0 = blockIdx.x * blockDim.x + threadIdx.x;
    int stride = gridDim.x * blockDim.x;
    unsigned f0 = 0, f1 = 0, f2 = 0;
    for (int i = 1 + 2 * i0; i < n_idx_words; i += 2 * stride)
        f0 |= (idx_words[i] != 0u);
    for (int i = i0; i < n_mask / 4; i += stride)
        f1 |= (mask_words[i] > 1u);
    for (int i = 1 + 2 * i0; i < n_mask / 2; i += 2 * stride)
        f2 |= (mask_words[i] != 0u);
    if (f0) atomicOr(&g_flags[0], 1u);
    if (f1) atomicOr(&g_flags[1], 1u);
    if (f2) atomicOr(&g_flags[2], 1u);
}

__global__ void finalize_sniff_kernel() {
    g_is64 = g_flags[0] ? 0 : 1;
    g_mask_mode = g_flags[1] ? 0 : (g_flags[2] ? 1 : 2);
}

// ---------------- prep: basesT to fp16 ----------------
__global__ void prep_bases_kernel(const float* __restrict__ bases) {
    // bases: (512,64) fp32. BT[n][k] = bases[k][n].
    for (int idx = blockIdx.x * blockDim.x + threadIdx.x; idx < 512 * 64;
         idx += gridDim.x * blockDim.x) {
        int n = idx >> 9, k = idx & 511;
        g_Bthi[n * 512 + k] = __float2half(bases[k * 64 + n]);
    }
}

// ---------------- K2: histogram of edge-direction targets ----------------
__global__ void hist_kernel(const int* src, const int* tgt, int E) {
    int is64 = g_is64;
    for (int i = blockIdx.x * blockDim.x + threadIdx.x; i < 2 * E;
         i += gridDim.x * blockDim.x) {
        int t = (i < E) ? ldidx(tgt, i, is64) : ldidx(src, i - E, is64);
        atomicAdd(&g_count[t], 1);
    }
}

// ---------------- K3: multi-block exclusive scan ----------------
__global__ void scan1_kernel(int N) {
    __shared__ int red[256];
    int b = blockIdx.x, t = threadIdx.x;
    int base = b * 1024 + t * 4;
    int s = 0;
#pragma unroll
    for (int j = 0; j < 4; j++) {
        int idx = base + j;
        if (idx < N) s += g_count[idx];
    }
    red[t] = s;
    __syncthreads();
    for (int off = 128; off > 0; off >>= 1) {
        if (t < off) red[t] += red[t + off];
        __syncthreads();
    }
    if (t == 0) g_bsum[b] = red[0];
}

__global__ void scan2_kernel(int nb, int N) {
    __shared__ int ts[256];
    int t = threadIdx.x;
    int v = (t < nb) ? g_bsum[t] : 0;
    ts[t] = v;
    __syncthreads();
    for (int off = 1; off < 256; off <<= 1) {
        int u = (t >= off) ? ts[t - off] : 0;
        __syncthreads();
        ts[t] += u;
        __syncthreads();
    }
    if (t < nb) g_boff[t] = ts[t] - v;
    if (t == 255) g_off[N] = ts[255];
}

__global__ void scan3_kernel(int N) {
    __shared__ int ts[256];
    int b = blockIdx.x, t = threadIdx.x;
    int base = b * 1024 + t * 4;
    int c[4];
    int s = 0;
#pragma unroll
    for (int j = 0; j < 4; j++) {
        int idx = base + j;
        c[j] = (idx < N) ? g_count[idx] : 0;
        s += c[j];
    }
    ts[t] = s;
    __syncthreads();
    for (int off = 1; off < 256; off <<= 1) {
        int u = (t >= off) ? ts[t - off] : 0;
        __syncthreads();
        ts[t] += u;
        __syncthreads();
    }
    int run = ts[t] - s + g_boff[b];
#pragma unroll
    for (int j = 0; j < 4; j++) {
        int idx = base + j;
        if (idx < N) {
            g_off[idx] = run;
            g_cur[idx] = run;
            run += c[j];
        }
    }
}

// ---------------- K4: scatter edges sorted by target ----------------
__global__ void scatter_kernel(const int* src, const int* tgt, const int* et,
                               int E) {
    int is64 = g_is64;
    for (int i = blockIdx.x * blockDim.x + threadIdx.x; i < 2 * E;
         i += gridDim.x * blockDim.x) {
        int e = (i < E) ? i : i - E;
        int s, t;
        if (i < E) { s = ldidx(src, e, is64); t = ldidx(tgt, e, is64); }
        else       { s = ldidx(tgt, e, is64); t = ldidx(src, e, is64); }
        int r = ldidx(et, e, is64);
        int pos = atomicAdd(&g_cur[t], 1);
        g_sorted[pos] = ((unsigned int)s << 4) | (unsigned int)r;
    }
}

// ---------------- K5: aggregation, warp per node, writes fp16 hi/lo ----------
__global__ void agg_kernel(const float* __restrict__ x,
                           const void* __restrict__ mask,
                           const float* __restrict__ att, int N) {
    __shared__ __align__(16) float4 att_s[34];
    int tid = threadIdx.x;
    if (tid < 34) att_s[tid] = ((const float4*)att)[tid];
    __syncthreads();

    int warp = tid >> 5, lane = tid & 31;
    int n = blockIdx.x * 8 + warp;
    if (n >= N) return;

    float acc0[8], acc1[8];
#pragma unroll
    for (int b = 0; b < 8; b++) { acc0[b] = 0.f; acc1[b] = 0.f; }

    int beg = g_off[n], end = g_off[n + 1];
    for (int i = beg; i < end; i++) {
        unsigned int p = g_sorted[i];
        int s = (int)(p >> 4);
        int r = (int)(p & 15u);
        float x0 = x[s * 64 + lane];
        float x1 = x[s * 64 + 32 + lane];
        float4 a0 = att_s[r * 2];
        float4 a1 = att_s[r * 2 + 1];
        float ar[8];
        *(float4*)&ar[0] = a0;
        *(float4*)&ar[4] = a1;
#pragma unroll
        for (int b = 0; b < 8; b++) {
            acc0[b] += ar[b] * x0;
            acc1[b] += ar[b] * x1;
        }
    }
    int mm = g_mask_mode;
    int keep;
    if (mm == 0)      keep = ((const unsigned char*)mask)[n];
    else if (mm == 1) keep = ((const int*)mask)[n];
    else              keep = ((const int*)mask)[2 * n];
    if (keep) {
        float x0 = x[n * 64 + lane];
        float x1 = x[n * 64 + 32 + lane];
        float4 a0 = att_s[32];
        float4 a1 = att_s[33];
        float ar[8];
        *(float4*)&ar[0] = a0;
        *(float4*)&ar[4] = a1;
#pragma unroll
        for (int b = 0; b < 8; b++) {
            acc0[b] += ar[b] * x0;
            acc1[b] += ar[b] * x1;
        }
    }
    size_t base = (size_t)n * 512;
#pragma unroll
    for (int b = 0; b < 8; b++) {
        float v0 = acc0[b], v1 = acc1[b];
        __half h0 = __float2half(v0);
        __half h1 = __float2half(v1);
        g_Ahi[base + b * 64 + lane]      = h0;
        g_Ahi[base + b * 64 + 32 + lane] = h1;
        g_Alo[base + b * 64 + lane]      = __float2half(v0 - __half2float(h0));
        g_Alo[base + b * 64 + 32 + lane] = __float2half(v1 - __half2float(h1));
    }
}

// ---------------- K6: mma.sync split-fp16 GEMM, double-buffered ----------------
// CTA: 128 nodes x 64 cols, 256 thr / 8 warps (warp grid 4x2, 32x32 tiles).
// D = Ahi@BT^T + Alo@BT^T, fp32 accum, B single fp16.
// smem: Bhi[64][520] @0 (66560 B); A bufs: [2][hi/lo][128][72]
#define OFF_BHI 0
#define OFF_A0H 66560
#define OFF_A0L 84992
#define OFF_A1H 103424
#define OFF_A1L 121856
#define SMEM_MM 140288
#define ABUF_SZ 36864   // hi+lo per buffer

__global__ __launch_bounds__(256, 1) void gemm_mm_kernel(
    float* __restrict__ out, int N) {
    extern __shared__ __align__(16) char sm[];
    uint32_t sbase = smem_u32(sm);
    int tid = threadIdx.x, wid = tid >> 5, lid = tid & 31;
    int nb = blockIdx.x * 128;
    int warp_m = (wid & 3) * 32;   // 0,32,64,96
    int warp_n = (wid >> 2) * 32;  // 0,32

    // ---- stage B once: 64 rows x 512 k fp16 ----
#pragma unroll
    for (int t = 0; t < 8; t++) {
        int idx = t * 256 + tid;
        int row = idx >> 5;
        int cb = (idx & 31) * 32;
        *(uint4*)(sm + OFF_BHI + row * 1040 + cb) =
            *(const uint4*)((const char*)g_Bthi + row * 1024 + cb);
        *(uint4*)(sm + OFF_BHI + row * 1040 + cb + 16) =
            *(const uint4*)((const char*)g_Bthi + row * 1024 + cb + 16);
    }

    // per-thread cp.async coordinates for one A chunk (128 rows x 128B, hi+lo)
    // 8 transfers of 16B per thread: 4 hi + 4 lo
    // stage chunk c into buffer (c & 1)
    auto stageA = [&](int c, uint32_t offH, uint32_t offL) {
#pragma unroll
        for (int t = 0; t < 4; t++) {
            int idx = t * 256 + tid;
            int row = idx >> 3;
            int cb = (idx & 7) * 16;
            size_t gb = (size_t)(nb + row) * 1024 + (size_t)c * 128 + cb;
            cp16(sbase + offH + row * 144 + cb, (const char*)g_Ahi + gb);
            cp16(sbase + offL + row * 144 + cb, (const char*)g_Alo + gb);
        }
        CP_COMMIT();
    };

    float acc[2][4][4];
#pragma unroll
    for (int mt = 0; mt < 2; mt++)
#pragma unroll
        for (int nt = 0; nt < 4; nt++)
#pragma unroll
            for (int q = 0; q < 4; q++) acc[mt][nt][q] = 0.f;

    // per-lane ldmatrix addresses
    uint32_t a_row0 = (uint32_t)(warp_m + (lid & 15));
    uint32_t a_kb = (uint32_t)(lid & 16);
    uint32_t a_off = a_row0 * 144 + a_kb;
    uint32_t b_row = (uint32_t)(warp_n + (lid & 7) + ((lid >> 4) & 1) * 8);
    uint32_t b_kb = (uint32_t)(((lid >> 3) & 1) * 16);
    uint32_t baddr0 = sbase + OFF_BHI + b_row * 1040 + b_kb;
    uint32_t baddr1 = baddr0 + 16 * 1040;

    stageA(0, OFF_A0H, OFF_A0L);

    for (int c = 0; c < 8; c++) {
        int cur = c & 1;
        if (c < 7)
            stageA(c + 1, cur ? OFF_A0H : OFF_A1H, cur ? OFF_A0L : OFF_A1L);
        if (c < 7) CP_WAIT(1); else CP_WAIT(0);
        __syncthreads();

        uint32_t ah0 = sbase + (cur ? OFF_A1H : OFF_A0H) + a_off;
        uint32_t al0 = sbase + (cur ? OFF_A1L : OFF_A0L) + a_off;

#pragma unroll
        for (int ks = 0; ks < 4; ks++) {
            uint32_t kb = (uint32_t)(ks * 32);
            uint32_t gkb = (uint32_t)(c * 128) + kb;
            uint32_t ahi[2][4], alo[2][4];
            ldsm4(ahi[0], ah0 + kb);
            ldsm4(ahi[1], ah0 + 16 * 144 + kb);
            ldsm4(alo[0], al0 + kb);
            ldsm4(alo[1], al0 + 16 * 144 + kb);
            uint32_t bhp[2][4];
            ldsm4(bhp[0], baddr0 + gkb);
            ldsm4(bhp[1], baddr1 + gkb);
#pragma unroll
            for (int mt = 0; mt < 2; mt++) {
#pragma unroll
                for (int nt = 0; nt < 4; nt++) {
                    const uint32_t* bf = &bhp[nt >> 1][(nt & 1) * 2];
                    mma16816(acc[mt][nt], ahi[mt], bf);
                    mma16816(acc[mt][nt], alo[mt], bf);
                }
            }
        }
        __syncthreads();
    }

    // ---- store ----
    int trow = lid >> 2, tcol = (lid & 3) * 2;
#pragma unroll
    for (int mt = 0; mt < 2; mt++) {
        int m0 = nb + warp_m + mt * 16 + trow;
#pragma unroll
        for (int nt = 0; nt < 4; nt++) {
            int col = warp_n + nt * 8 + tcol;
            if (m0 < N)
                *(float2*)(out + (size_t)m0 * 64 + col) =
                    make_float2(acc[mt][nt][0], acc[mt][nt][1]);
            if (m0 + 8 < N)
                *(float2*)(out + (size_t)(m0 + 8) * 64 + col) =
                    make_float2(acc[mt][nt][2], acc[mt][nt][3]);
        }
    }
}

// ---------------- launch ----------------
extern "C" void kernel_launch(void* const* d_in, const int* in_sizes, int n_in,
                              void* d_out, int out_size) {
    const float* x = (const float*)d_in[0];
    const void* mask = d_in[1];
    const int* src = (const int*)d_in[2];
    const int* tgt = (const int*)d_in[3];
    const int* et = (const int*)d_in[4];
    const float* bases = (const float*)d_in[5];
    const float* att = (const float*)d_in[6];
    float* out = (float*)d_out;

    int N = in_sizes[1];
    int E = in_sizes[2];
    int nb = (N + 1023) / 1024;

    cudaFuncSetAttribute(gemm_mm_kernel,
                         cudaFuncAttributeMaxDynamicSharedMemorySize, SMEM_MM);

    zero_kernel<<<256, 256>>>(N);
    sniff_kernel<<<256, 256>>>((const unsigned int*)d_in[2], E,
                               (const unsigned int*)d_in[1], N);
    finalize_sniff_kernel<<<1, 1>>>();
    prep_bases_kernel<<<128, 256>>>(bases);
    hist_kernel<<<3200, 256>>>(src, tgt, E);
    scan1_kernel<<<nb, 256>>>(N);
    scan2_kernel<<<1, 256>>>(nb, N);
    scan3_kernel<<<nb, 256>>>(N);
    scatter_kernel<<<3200, 256>>>(src, tgt, et, E);
    agg_kernel<<<(N + 7) / 8, 256>>>(x, mask, att, N);
    gemm_mm_kernel<<<(N + 127) / 128, 256, SMEM_MM>>>(out, N);
}

// round 9
// speedup vs baseline: 4.2822x; 1.3166x over previous
#include <cuda_runtime.h>
#include <cuda_fp16.h>
#include <cstdint>

#define NN 200000
#define NE 800000
#define NPAD 200064   // 1563 * 128

// ---------------- device scratch (no allocations allowed) ----------------
__device__ int g_is64;
__device__ int g_mask_mode;  // 0 = byte bool, 1 = int32, 2 = int64
__device__ unsigned int g_flags[3];
__device__ int g_count[NN];
__device__ int g_off[NN + 1];
__device__ int g_cur[NN];
__device__ int g_bsum[256];
__device__ int g_boff[256];
__device__ unsigned int g_sorted[2 * NE];
__device__ __half g_Ahi[(size_t)NPAD * 512];  // 205 MB
__device__ __half g_Bthi[64 * 512];           // basesT fp16 (n-major, k-contig)

// ---------------- helpers ----------------
__device__ __forceinline__ int ldidx(const int* p, int i, int is64) {
    return is64 ? p[2 * i] : p[i];
}
__device__ __forceinline__ uint32_t smem_u32(const void* p) {
    uint32_t a;
    asm("{ .reg .u64 t; cvta.to.shared.u64 t, %1; cvt.u32.u64 %0, t; }"
        : "=r"(a) : "l"(p));
    return a;
}
__device__ __forceinline__ void ldsm4(uint32_t* r, uint32_t addr) {
    asm volatile("ldmatrix.sync.aligned.m8n8.x4.shared.b16 {%0,%1,%2,%3}, [%4];"
                 : "=r"(r[0]), "=r"(r[1]), "=r"(r[2]), "=r"(r[3]) : "r"(addr));
}
__device__ __forceinline__ void mma16816(float* c, const uint32_t* a,
                                         const uint32_t* b) {
    asm volatile(
        "mma.sync.aligned.m16n8k16.row.col.f32.f16.f16.f32 "
        "{%0,%1,%2,%3}, {%4,%5,%6,%7}, {%8,%9}, {%0,%1,%2,%3};"
        : "+f"(c[0]), "+f"(c[1]), "+f"(c[2]), "+f"(c[3])
        : "r"(a[0]), "r"(a[1]), "r"(a[2]), "r"(a[3]), "r"(b[0]), "r"(b[1]));
}
__device__ __forceinline__ void cp16(uint32_t saddr, const void* gptr) {
    asm volatile("cp.async.cg.shared.global [%0], [%1], 16;"
                 :: "r"(saddr), "l"(gptr) : "memory");
}
#define CP_COMMIT() asm volatile("cp.async.commit_group;" ::: "memory")
#define CP_WAIT(n)  asm volatile("cp.async.wait_group %0;" :: "n"(n) : "memory")

// ---------------- K0a: zero hist + flags ----------------
__global__ void zero_kernel(int N) {
    int i0 = blockIdx.x * blockDim.x + threadIdx.x;
    if (i0 < 3) g_flags[i0] = 0u;
    for (int i = i0; i < N; i += gridDim.x * blockDim.x) g_count[i] = 0;
}

// ---------------- K0b: parallel dtype sniff ----------------
__global__ void sniff_kernel(const unsigned int* idx_words, int n_idx_words,
                             const unsigned int* mask_words, int n_mask) {
    int i0 = blockIdx.x * blockDim.x + threadIdx.x;
    int stride = gridDim.x * blockDim.x;
    unsigned f0 = 0, f1 = 0, f2 = 0;
    for (int i = 1 + 2 * i0; i < n_idx_words; i += 2 * stride)
        f0 |= (idx_words[i] != 0u);
    for (int i = i0; i < n_mask / 4; i += stride)
        f1 |= (mask_words[i] > 1u);
    for (int i = 1 + 2 * i0; i < n_mask / 2; i += 2 * stride)
        f2 |= (mask_words[i] != 0u);
    if (f0) atomicOr(&g_flags[0], 1u);
    if (f1) atomicOr(&g_flags[1], 1u);
    if (f2) atomicOr(&g_flags[2], 1u);
}

__global__ void finalize_sniff_kernel() {
    g_is64 = g_flags[0] ? 0 : 1;
    g_mask_mode = g_flags[1] ? 0 : (g_flags[2] ? 1 : 2);
}

// ---------------- prep: basesT to fp16 ----------------
__global__ void prep_bases_kernel(const float* __restrict__ bases) {
    // bases: (512,64) fp32. BT[n][k] = bases[k][n].
    for (int idx = blockIdx.x * blockDim.x + threadIdx.x; idx < 512 * 64;
         idx += gridDim.x * blockDim.x) {
        int n = idx >> 9, k = idx & 511;
        g_Bthi[n * 512 + k] = __float2half(bases[k * 64 + n]);
    }
}

// ---------------- K2: histogram of edge-direction targets ----------------
__global__ void hist_kernel(const int* src, const int* tgt, int E) {
    int is64 = g_is64;
    for (int i = blockIdx.x * blockDim.x + threadIdx.x; i < 2 * E;
         i += gridDim.x * blockDim.x) {
        int t = (i < E) ? ldidx(tgt, i, is64) : ldidx(src, i - E, is64);
        atomicAdd(&g_count[t], 1);
    }
}

// ---------------- K3: multi-block exclusive scan ----------------
__global__ void scan1_kernel(int N) {
    __shared__ int red[256];
    int b = blockIdx.x, t = threadIdx.x;
    int base = b * 1024 + t * 4;
    int s = 0;
#pragma unroll
    for (int j = 0; j < 4; j++) {
        int idx = base + j;
        if (idx < N) s += g_count[idx];
    }
    red[t] = s;
    __syncthreads();
    for (int off = 128; off > 0; off >>= 1) {
        if (t < off) red[t] += red[t + off];
        __syncthreads();
    }
    if (t == 0) g_bsum[b] = red[0];
}

__global__ void scan2_kernel(int nb, int N) {
    __shared__ int ts[256];
    int t = threadIdx.x;
    int v = (t < nb) ? g_bsum[t] : 0;
    ts[t] = v;
    __syncthreads();
    for (int off = 1; off < 256; off <<= 1) {
        int u = (t >= off) ? ts[t - off] : 0;
        __syncthreads();
        ts[t] += u;
        __syncthreads();
    }
    if (t < nb) g_boff[t] = ts[t] - v;
    if (t == 255) g_off[N] = ts[255];
}

__global__ void scan3_kernel(int N) {
    __shared__ int ts[256];
    int b = blockIdx.x, t = threadIdx.x;
    int base = b * 1024 + t * 4;
    int c[4];
    int s = 0;
#pragma unroll
    for (int j = 0; j < 4; j++) {
        int idx = base + j;
        c[j] = (idx < N) ? g_count[idx] : 0;
        s += c[j];
    }
    ts[t] = s;
    __syncthreads();
    for (int off = 1; off < 256; off <<= 1) {
        int u = (t >= off) ? ts[t - off] : 0;
        __syncthreads();
        ts[t] += u;
        __syncthreads();
    }
    int run = ts[t] - s + g_boff[b];
#pragma unroll
    for (int j = 0; j < 4; j++) {
        int idx = base + j;
        if (idx < N) {
            g_off[idx] = run;
            g_cur[idx] = run;
            run += c[j];
        }
    }
}

// ---------------- K4: scatter edges sorted by target ----------------
__global__ void scatter_kernel(const int* src, const int* tgt, const int* et,
                               int E) {
    int is64 = g_is64;
    for (int i = blockIdx.x * blockDim.x + threadIdx.x; i < 2 * E;
         i += gridDim.x * blockDim.x) {
        int e = (i < E) ? i : i - E;
        int s, t;
        if (i < E) { s = ldidx(src, e, is64); t = ldidx(tgt, e, is64); }
        else       { s = ldidx(tgt, e, is64); t = ldidx(src, e, is64); }
        int r = ldidx(et, e, is64);
        int pos = atomicAdd(&g_cur[t], 1);
        g_sorted[pos] = ((unsigned int)s << 4) | (unsigned int)r;
    }
}

// ---------------- K5: aggregation, warp per node, writes fp16 ----------
__global__ void agg_kernel(const float* __restrict__ x,
                           const void* __restrict__ mask,
                           const float* __restrict__ att, int N) {
    __shared__ __align__(16) float4 att_s[34];
    int tid = threadIdx.x;
    if (tid < 34) att_s[tid] = ((const float4*)att)[tid];
    __syncthreads();

    int warp = tid >> 5, lane = tid & 31;
    int n = blockIdx.x * 8 + warp;
    if (n >= N) return;

    float acc0[8], acc1[8];
#pragma unroll
    for (int b = 0; b < 8; b++) { acc0[b] = 0.f; acc1[b] = 0.f; }

    int beg = g_off[n], end = g_off[n + 1];
    for (int i = beg; i < end; i++) {
        unsigned int p = g_sorted[i];
        int s = (int)(p >> 4);
        int r = (int)(p & 15u);
        float x0 = x[s * 64 + lane];
        float x1 = x[s * 64 + 32 + lane];
        float4 a0 = att_s[r * 2];
        float4 a1 = att_s[r * 2 + 1];
        float ar[8];
        *(float4*)&ar[0] = a0;
        *(float4*)&ar[4] = a1;
#pragma unroll
        for (int b = 0; b < 8; b++) {
            acc0[b] += ar[b] * x0;
            acc1[b] += ar[b] * x1;
        }
    }
    int mm = g_mask_mode;
    int keep;
    if (mm == 0)      keep = ((const unsigned char*)mask)[n];
    else if (mm == 1) keep = ((const int*)mask)[n];
    else              keep = ((const int*)mask)[2 * n];
    if (keep) {
        float x0 = x[n * 64 + lane];
        float x1 = x[n * 64 + 32 + lane];
        float4 a0 = att_s[32];
        float4 a1 = att_s[33];
        float ar[8];
        *(float4*)&ar[0] = a0;
        *(float4*)&ar[4] = a1;
#pragma unroll
        for (int b = 0; b < 8; b++) {
            acc0[b] += ar[b] * x0;
            acc1[b] += ar[b] * x1;
        }
    }
    size_t base = (size_t)n * 512;
#pragma unroll
    for (int b = 0; b < 8; b++) {
        g_Ahi[base + b * 64 + lane]      = __float2half(acc0[b]);
        g_Ahi[base + b * 64 + 32 + lane] = __float2half(acc1[b]);
    }
}

// ---------------- K6: mma.sync fp16 GEMM, double-buffered, 2 CTAs/SM ------
// CTA: 128 nodes x 64 cols, 256 thr / 8 warps (warp grid 4x2, 32x32 tiles).
// D = A@BT^T, fp16 x fp16 -> fp32 accum.
// smem: B[64][520] @0 (66560 B); A bufs: [2][128][72] (2x18432)
#define OFF_B  0
#define OFF_A0 66560
#define OFF_A1 84992
#define SMEM_MM 103424

__global__ __launch_bounds__(256, 2) void gemm_mm_kernel(
    float* __restrict__ out, int N) {
    extern __shared__ __align__(16) char sm[];
    uint32_t sbase = smem_u32(sm);
    int tid = threadIdx.x, wid = tid >> 5, lid = tid & 31;
    int nb = blockIdx.x * 128;
    int warp_m = (wid & 3) * 32;   // 0,32,64,96
    int warp_n = (wid >> 2) * 32;  // 0,32

    // ---- stage B once: 64 rows x 512 k fp16 ----
#pragma unroll
    for (int t = 0; t < 8; t++) {
        int idx = t * 256 + tid;
        int row = idx >> 5;
        int cb = (idx & 31) * 32;
        *(uint4*)(sm + OFF_B + row * 1040 + cb) =
            *(const uint4*)((const char*)g_Bthi + row * 1024 + cb);
        *(uint4*)(sm + OFF_B + row * 1040 + cb + 16) =
            *(const uint4*)((const char*)g_Bthi + row * 1024 + cb + 16);
    }

    // stage one A chunk (128 rows x 128B): 2 x 16B per thread
    auto stageA = [&](int c, uint32_t offA) {
#pragma unroll
        for (int t = 0; t < 2; t++) {
            int idx = t * 256 + tid;
            int row = idx >> 2;
            int cb = (idx & 3) * 32;
            size_t gb = (size_t)(nb + row) * 1024 + (size_t)c * 128 + cb;
            cp16(sbase + offA + row * 144 + cb, (const char*)g_Ahi + gb);
            cp16(sbase + offA + row * 144 + cb + 16, (const char*)g_Ahi + gb + 16);
        }
        CP_COMMIT();
    };

    float acc[2][4][4];
#pragma unroll
    for (int mt = 0; mt < 2; mt++)
#pragma unroll
        for (int nt = 0; nt < 4; nt++)
#pragma unroll
            for (int q = 0; q < 4; q++) acc[mt][nt][q] = 0.f;

    // per-lane ldmatrix addresses
    uint32_t a_row0 = (uint32_t)(warp_m + (lid & 15));
    uint32_t a_kb = (uint32_t)(lid & 16);
    uint32_t a_off = a_row0 * 144 + a_kb;
    uint32_t b_row = (uint32_t)(warp_n + (lid & 7) + ((lid >> 4) & 1) * 8);
    uint32_t b_kb = (uint32_t)(((lid >> 3) & 1) * 16);
    uint32_t baddr0 = sbase + OFF_B + b_row * 1040 + b_kb;
    uint32_t baddr1 = baddr0 + 16 * 1040;

    stageA(0, OFF_A0);

    for (int c = 0; c < 8; c++) {
        int cur = c & 1;
        if (c < 7) stageA(c + 1, cur ? OFF_A0 : OFF_A1);
        if (c < 7) CP_WAIT(1); else CP_WAIT(0);
        __syncthreads();

        uint32_t ah0 = sbase + (cur ? OFF_A1 : OFF_A0) + a_off;

#pragma unroll
        for (int ks = 0; ks < 4; ks++) {
            uint32_t kb = (uint32_t)(ks * 32);
            uint32_t gkb = (uint32_t)(c * 128) + kb;
            uint32_t ahi[2][4];
            ldsm4(ahi[0], ah0 + kb);
            ldsm4(ahi[1], ah0 + 16 * 144 + kb);
            uint32_t bhp[2][4];
            ldsm4(bhp[0], baddr0 + gkb);
            ldsm4(bhp[1], baddr1 + gkb);
#pragma unroll
            for (int mt = 0; mt < 2; mt++) {
#pragma unroll
                for (int nt = 0; nt < 4; nt++) {
                    const uint32_t* bf = &bhp[nt >> 1][(nt & 1) * 2];
                    mma16816(acc[mt][nt], ahi[mt], bf);
                }
            }
        }
        __syncthreads();
    }

    // ---- store ----
    int trow = lid >> 2, tcol = (lid & 3) * 2;
#pragma unroll
    for (int mt = 0; mt < 2; mt++) {
        int m0 = nb + warp_m + mt * 16 + trow;
#pragma unroll
        for (int nt = 0; nt < 4; nt++) {
            int col = warp_n + nt * 8 + tcol;
            if (m0 < N)
                *(float2*)(out + (size_t)m0 * 64 + col) =
                    make_float2(acc[mt][nt][0], acc[mt][nt][1]);
            if (m0 + 8 < N)
                *(float2*)(out + (size_t)(m0 + 8) * 64 + col) =
                    make_float2(acc[mt][nt][2], acc[mt][nt][3]);
        }
    }
}

// ---------------- launch ----------------
extern "C" void kernel_launch(void* const* d_in, const int* in_sizes, int n_in,
                              void* d_out, int out_size) {
    const float* x = (const float*)d_in[0];
    const void* mask = d_in[1];
    const int* src = (const int*)d_in[2];
    const int* tgt = (const int*)d_in[3];
    const int* et = (const int*)d_in[4];
    const float* bases = (const float*)d_in[5];
    const float* att = (const float*)d_in[6];
    float* out = (float*)d_out;

    int N = in_sizes[1];
    int E = in_sizes[2];
    int nb = (N + 1023) / 1024;

    cudaFuncSetAttribute(gemm_mm_kernel,
                         cudaFuncAttributeMaxDynamicSharedMemorySize, SMEM_MM);

    zero_kernel<<<256, 256>>>(N);
    sniff_kernel<<<256, 256>>>((const unsigned int*)d_in[2], E,
                               (const unsigned int*)d_in[1], N);
    finalize_sniff_kernel<<<1, 1>>>();
    prep_bases_kernel<<<128, 256>>>(bases);
    hist_kernel<<<3200, 256>>>(src, tgt, E);
    scan1_kernel<<<nb, 256>>>(N);
    scan2_kernel<<<1, 256>>>(nb, N);
    scan3_kernel<<<nb, 256>>>(N);
    scatter_kernel<<<3200, 256>>>(src, tgt, et, E);
    agg_kernel<<<(N + 7) / 8, 256>>>(x, mask, att, N);
    gemm_mm_kernel<<<(N + 127) / 128, 256, SMEM_MM>>>(out, N);
}